// round 13
// baseline (speedup 1.0000x reference)
#include <cuda_runtime.h>
#include <math.h>

#define Tn 1024
#define Bn 128

// ---------------- static device scratch ----------------
// g_XP[((t*4 + g)*768 + col)*128 + b]
__device__ float g_XP[(size_t)Bn * Tn * 3072];
// g_H / g_RH: [gi*8192 + k*32 + b32], gi = g*4 + pgroup
__device__ float g_H [16 * 8192];
__device__ float g_RH[16 * 8192];
// counters: [(gi*4 + which)*16], which: 0=rh_half0,1=rh_half1,2=h_half0,3=h_half1
__device__ unsigned g_cnt[1024];
__device__ unsigned g_headbar;

// ---------------- f32x2 helpers ----------------
static __device__ __forceinline__ unsigned long long pk2(float lo, float hi) {
    unsigned long long r;
    asm("mov.b64 %0, {%1, %2};" : "=l"(r) : "f"(lo), "f"(hi));
    return r;
}
static __device__ __forceinline__ void up2(unsigned long long v, float& lo, float& hi) {
    asm("mov.b64 {%0, %1}, %2;" : "=f"(lo), "=f"(hi) : "l"(v));
}
static __device__ __forceinline__ void fma2(unsigned long long& d,
                                            unsigned long long a,
                                            unsigned long long b) {
    asm("fma.rn.f32x2 %0, %1, %2, %0;" : "+l"(d) : "l"(a), "l"(b));
}
static __device__ __forceinline__ void add2(unsigned long long& d, unsigned long long a) {
    asm("add.rn.f32x2 %0, %0, %1;" : "+l"(d) : "l"(a));
}
static __device__ __forceinline__ float sigf(float x) {
    return 1.0f / (1.0f + __expf(-x));
}
static __device__ __forceinline__ float tanhfast(float x) {
    float e = __expf(2.0f * x);
    return 1.0f - 2.0f / (e + 1.0f);
}

// ---------------- cp.async helpers ----------------
static __device__ __forceinline__ void cpa16(void* smem, const void* gmem) {
    unsigned s = (unsigned)__cvta_generic_to_shared(smem);
    asm volatile("cp.async.cg.shared.global [%0], [%1], 16;" :: "r"(s), "l"(gmem));
}
#define CPA_COMMIT() asm volatile("cp.async.commit_group;")
#define CPA_WAIT(n)  asm volatile("cp.async.wait_group %0;" :: "n"(n))

// single-thread poll, then CTA-wide release
static __device__ __forceinline__ void wait_cnt(volatile unsigned* c, unsigned tgt) {
    if (threadIdx.x == 0) {
        while (*c < tgt) { __nanosleep(20); }
    }
    __syncthreads();
}

// ---------------- xproj SGEMM (f32x2, transposed output) + folded init ----------------
__global__ void __launch_bounds__(256) xproj_kernel(
    const float* __restrict__ X,
    const float* __restrict__ W0, const float* __restrict__ W1,
    const float* __restrict__ W2, const float* __restrict__ W3,
    const float* __restrict__ b0, const float* __restrict__ b1,
    const float* __restrict__ b2, const float* __restrict__ b3,
    const float* __restrict__ ich0, const float* __restrict__ cih0,
    float* __restrict__ out)
{
    __shared__ float As[8][128];
    __shared__ float Bs[8][128];

    const int t_  = blockIdx.y;
    const int n0  = blockIdx.x * 128;
    const int g   = n0 / 768;
    const int nc  = n0 - g * 768;
    const float* W    = (g == 0) ? W0 : (g == 1) ? W1 : (g == 2) ? W2 : W3;
    const float* bias = (g == 0) ? b0 : (g == 1) ? b1 : (g == 2) ? b2 : b3;

    const int tid  = threadIdx.x;
    const int warp = tid >> 5, lane = tid & 31;
    const int row0 = (warp & 3) * 32 + (lane >> 3) * 8;
    const int col0 = (warp >> 2) * 64 + (lane & 7) * 8;

    const int am = tid >> 1, ak = (tid & 1) * 4;
    const int bk = tid >> 5, bn = (tid & 31) * 4;

    // ---- folded init (blocks with t_==0) ----
    if (t_ == 0) {
        float* ci = out + 32768;
        for (int i = blockIdx.x * 256 + tid; i < Bn * 256; i += 24 * 256) {
            int b = i >> 8, d = i & 255;
            ci[((size_t)b * Tn) * 512 + d] = 0.0f;
            ci[((size_t)b * Tn + (Tn - 1)) * 512 + 256 + d] = 0.0f;
        }
        for (int i = blockIdx.x * 256 + tid; i < 1024; i += 24 * 256)
            g_cnt[i] = 0u;
        if (blockIdx.x == 0 && tid == 0) g_headbar = 0u;
        for (int i = blockIdx.x * 256 + tid; i < 16 * 8192; i += 24 * 256) {
            int gi = i >> 13;
            int gg = gi >> 2;
            int k  = (i >> 5) & 255;
            const float* h0 = (gg < 2) ? ich0 : cih0;
            g_H[i] = h0[(gg & 1) * 256 + k];
        }
    }

    unsigned long long acc[8][4];
    #pragma unroll
    for (int i = 0; i < 8; i++)
        #pragma unroll
        for (int j = 0; j < 4; j++) acc[i][j] = 0ULL;

    for (int k0 = 0; k0 < 256; k0 += 8) {
        float4 av = __ldg((const float4*)&X[(size_t)am * (Tn * 256) + t_ * 256 + k0 + ak]);
        float4 bv = __ldg((const float4*)&W[(size_t)(k0 + bk) * 768 + nc + bn]);
        __syncthreads();
        As[ak + 0][am] = av.x; As[ak + 1][am] = av.y;
        As[ak + 2][am] = av.z; As[ak + 3][am] = av.w;
        *(float4*)&Bs[bk][bn] = bv;
        __syncthreads();

        #pragma unroll
        for (int kk = 0; kk < 8; ++kk) {
            float4 a0 = *(const float4*)&As[kk][row0];
            float4 a1 = *(const float4*)&As[kk][row0 + 4];
            ulonglong2 b01 = *(const ulonglong2*)&Bs[kk][col0];
            ulonglong2 b23 = *(const ulonglong2*)&Bs[kk][col0 + 4];
            float ar[8] = {a0.x, a0.y, a0.z, a0.w, a1.x, a1.y, a1.z, a1.w};
            #pragma unroll
            for (int i = 0; i < 8; i++) {
                unsigned long long ai = pk2(ar[i], ar[i]);
                fma2(acc[i][0], ai, b01.x);
                fma2(acc[i][1], ai, b01.y);
                fma2(acc[i][2], ai, b23.x);
                fma2(acc[i][3], ai, b23.y);
            }
        }
    }

    float c[8][8];
    #pragma unroll
    for (int i = 0; i < 8; i++) {
        up2(acc[i][0], c[i][0], c[i][1]);
        up2(acc[i][1], c[i][2], c[i][3]);
        up2(acc[i][2], c[i][4], c[i][5]);
        up2(acc[i][3], c[i][6], c[i][7]);
    }
    #pragma unroll
    for (int j = 0; j < 8; j++) {
        float bb = bias[nc + col0 + j];
        size_t base = ((size_t)(t_ * 4 + g) * 768 + nc + col0 + j) * 128 + row0;
        float4 v0 = make_float4(c[0][j] + bb, c[1][j] + bb, c[2][j] + bb, c[3][j] + bb);
        float4 v1 = make_float4(c[4][j] + bb, c[5][j] + bb, c[6][j] + bb, c[7][j] + bb);
        __stcg((float4*)&g_XP[base],     v0);
        __stcg((float4*)&g_XP[base + 4], v1);
    }
}

// ---------------- scan smem layout (floats) ----------------
#define HS_OFF   0                        // 8192 : H/RH slice [256][32]
#define U1_OFF   8192                     // 8192 : zr U slab [256][32] (16 z | 16 r)
#define U2_OFF   16384                    // 4096 : hh U slab [256][16]
#define XP_OFF   20480                    // 3072 : XP double buffer [2][48][32]
#define ZS_OFF   23552                    // 512  : z gate [16][32]
#define HSV_OFF  24064                    // 512  : saved old-H [16][32]
#define RS_OFF   24576                    // 512  : phase2 split-k partials (256 u64)
#define SCAN_SMEM_FLOATS 25088
#define SCAN_SMEM_BYTES  (SCAN_SMEM_FLOATS * 4)   // 100352 B -> 2 CTAs/SM

// ---------------- persistent scan: 256 CTAs = 4 GRU x 4 bgroup x 16 colslice ----------------
__global__ void __launch_bounds__(256, 2) scan_kernel(
    const float* __restrict__ U0, const float* __restrict__ U1,
    const float* __restrict__ U2, const float* __restrict__ U3,
    const float* __restrict__ Wm, const float* __restrict__ bm,
    const float* __restrict__ Wlv, const float* __restrict__ blv,
    float* __restrict__ out)
{
    extern __shared__ float sm[];
    float* Hs   = sm + HS_OFF;
    float* U1s  = sm + U1_OFF;
    float* U2s  = sm + U2_OFF;
    float* XPd  = sm + XP_OFF;
    float* Zs   = sm + ZS_OFF;
    float* HsSv = sm + HSV_OFF;
    unsigned long long* Rs = (unsigned long long*)(sm + RS_OFF);

    const int g   = blockIdx.x >> 6;
    const int pg  = (blockIdx.x >> 4) & 3;
    const int cs  = blockIdx.x & 15;
    const int d0  = cs * 16;
    const int gi  = g * 4 + pg;
    const int tid = threadIdx.x;
    const int b   = tid & 31;
    const int jo  = tid >> 5;              // 0..7
    const int half = cs >> 3;
    const float* U = (g == 0) ? U0 : (g == 1) ? U1 : (g == 2) ? U2 : U3;

    volatile unsigned* rh0c = &g_cnt[(gi * 4 + 0) * 16];
    volatile unsigned* rh1c = &g_cnt[(gi * 4 + 1) * 16];
    volatile unsigned* h0c  = &g_cnt[(gi * 4 + 2) * 16];
    volatile unsigned* h1c  = &g_cnt[(gi * 4 + 3) * 16];
    unsigned* my_rh = (unsigned*)&g_cnt[(gi * 4 + half) * 16];
    unsigned* my_h  = (unsigned*)&g_cnt[(gi * 4 + 2 + half) * 16];

    // resident U slabs
    for (int i = tid; i < 256 * 32; i += 256) {
        int k = i >> 5, jj = i & 31;
        int col = (jj < 16) ? (d0 + jj) : (256 + d0 + (jj - 16));
        U1s[i] = U[k * 768 + col];
    }
    for (int i = tid; i < 256 * 16; i += 256) {
        int k = i >> 4, jj = i & 15;
        U2s[i] = U[k * 768 + 512 + d0 + jj];
    }

    float* myH  = g_H  + gi * 8192;
    float* myRH = g_RH + gi * 8192;
    float* ci   = out + 32768;

    // thread tiles
    const bool zw = (jo < 4);
    const int j1 = zw ? jo * 4 : 16 + (jo - 4) * 4;   // phase1: 4 cols
    const int j2 = (jo & 3) * 4;                       // phase2: 4 cols, split-k
    const int kb2 = (jo < 4) ? 0 : 128;

    // ---- prologue: stage H(0) + XP(0) ----
    #pragma unroll
    for (int ch = 0; ch < 2; ch++) {
        #pragma unroll
        for (int r = 0; r < 4; r++)
            cpa16(Hs + ch * 4096 + (r * 256 + tid) * 4,
                  myH + ch * 4096 + (r * 256 + tid) * 4);
        CPA_COMMIT();
    }
    {
        int t0 = (g & 1) ? (Tn - 1) : 0;
        const float* xpb = g_XP + ((size_t)t0 * 4 + g) * 98304;
        for (int idx = tid; idx < 384; idx += 256) {
            int cl = idx >> 3, seg = idx & 7;
            int gcol = (cl < 16) ? (d0 + cl) : (cl < 32) ? (256 + d0 + cl - 16)
                                             : (512 + d0 + cl - 32);
            cpa16(XPd + cl * 32 + seg * 4, xpb + gcol * 128 + pg * 32 + seg * 4);
        }
        CPA_COMMIT();
    }
    CPA_WAIT(0);
    __syncthreads();

    for (int s = 0; s < Tn; s++) {
        const float* XPc = XPd + (s & 1) * 1536;

        // ---- prefetch XP(s+1) ----
        {
            int sn = (s < Tn - 1) ? (s + 1) : s;
            int tn_ = (g & 1) ? (Tn - 1 - sn) : sn;
            const float* xpb = g_XP + ((size_t)tn_ * 4 + g) * 98304;
            float* dst = XPd + ((s + 1) & 1) * 1536;
            for (int idx = tid; idx < 384; idx += 256) {
                int cl = idx >> 3, seg = idx & 7;
                int gcol = (cl < 16) ? (d0 + cl) : (cl < 32) ? (256 + d0 + cl - 16)
                                                 : (512 + d0 + cl - 32);
                cpa16(dst + cl * 32 + seg * 4, xpb + gcol * 128 + pg * 32 + seg * 4);
            }
            CPA_COMMIT();
        }

        unsigned long long acc[2];
        acc[0] = pk2(XPc[(j1 + 0) * 32 + b], XPc[(j1 + 1) * 32 + b]);
        acc[1] = pk2(XPc[(j1 + 2) * 32 + b], XPc[(j1 + 3) * 32 + b]);

        // ---- phased H staging (s>0) ----
        if (s > 0) {
            wait_cnt(h0c, (unsigned)(s * 8));
            #pragma unroll
            for (int r = 0; r < 4; r++)
                cpa16(Hs + (r * 256 + tid) * 4, myH + (r * 256 + tid) * 4);
            CPA_COMMIT();
            wait_cnt(h1c, (unsigned)(s * 8));
            #pragma unroll
            for (int r = 0; r < 4; r++)
                cpa16(Hs + 4096 + (r * 256 + tid) * 4, myH + 4096 + (r * 256 + tid) * 4);
            CPA_COMMIT();
        }

        // ---- phase 1: zr pre-activation (all 8 warps, 4j x 1b, full k) ----
        CPA_WAIT(1);
        __syncthreads();
        {
            const float* u1p = U1s + j1;
            const float* hp  = Hs + b;
            #pragma unroll 8
            for (int k = 0; k < 128; k++) {
                ulonglong2 ua = *(const ulonglong2*)(u1p);
                float h = *hp;
                unsigned long long hd = pk2(h, h);
                fma2(acc[0], ua.x, hd); fma2(acc[1], ua.y, hd);
                u1p += 32; hp += 32;
            }
        }
        CPA_WAIT(0);
        __syncthreads();
        {
            const float* u1p = U1s + 128 * 32 + j1;
            const float* hp  = Hs + 128 * 32 + b;
            #pragma unroll 8
            for (int k = 0; k < 128; k++) {
                ulonglong2 ua = *(const ulonglong2*)(u1p);
                float h = *hp;
                unsigned long long hd = pk2(h, h);
                fma2(acc[0], ua.x, hd); fma2(acc[1], ua.y, hd);
                u1p += 32; hp += 32;
            }
        }

        // epilogue: z -> Zs, r -> rh -> gmem, save own old-H rows
        {
            float v[4];
            up2(acc[0], v[0], v[1]);
            up2(acc[1], v[2], v[3]);
            if (zw) {
                #pragma unroll
                for (int j = 0; j < 4; j++)
                    Zs[(j1 + j) * 32 + b] = sigf(v[j]);
            } else {
                #pragma unroll
                for (int j = 0; j < 4; j++) {
                    int row = d0 + (j1 - 16) + j;
                    float rh = sigf(v[j]) * Hs[row * 32 + b];
                    __stcg(myRH + row * 32 + b, rh);
                }
            }
            HsSv[tid]       = Hs[(d0 + (tid >> 5)) * 32 + (tid & 31)];
            HsSv[tid + 256] = Hs[(d0 + 8 + (tid >> 5)) * 32 + (tid & 31)];
        }
        __syncthreads();
        if (tid == 0) { __threadfence(); atomicAdd(my_rh, 1u); }

        // ---- phased RH staging ----
        wait_cnt(rh0c, (unsigned)((s + 1) * 8));
        #pragma unroll
        for (int r = 0; r < 4; r++)
            cpa16(Hs + (r * 256 + tid) * 4, myRH + (r * 256 + tid) * 4);
        CPA_COMMIT();
        wait_cnt(rh1c, (unsigned)((s + 1) * 8));
        #pragma unroll
        for (int r = 0; r < 4; r++)
            cpa16(Hs + 4096 + (r * 256 + tid) * 4, myRH + 4096 + (r * 256 + tid) * 4);
        CPA_COMMIT();

        CPA_WAIT(0);
        __syncthreads();

        // ---- phase 2: candidate, split-k across warp halves ----
        unsigned long long acc2[2];
        if (jo < 4) {
            acc2[0] = pk2(XPc[(32 + j2 + 0) * 32 + b], XPc[(32 + j2 + 1) * 32 + b]);
            acc2[1] = pk2(XPc[(32 + j2 + 2) * 32 + b], XPc[(32 + j2 + 3) * 32 + b]);
        } else {
            acc2[0] = 0ULL; acc2[1] = 0ULL;
        }
        {
            const float* u2p = U2s + kb2 * 16 + j2;
            const float* hp  = Hs + kb2 * 32 + b;
            #pragma unroll 8
            for (int k = 0; k < 128; k++) {
                ulonglong2 u = *(const ulonglong2*)(u2p);
                float h = *hp;
                unsigned long long hd = pk2(h, h);
                fma2(acc2[0], u.x, hd); fma2(acc2[1], u.y, hd);
                u2p += 16; hp += 32;
            }
        }
        if (jo >= 4) {
            Rs[(tid - 128) * 2]     = acc2[0];
            Rs[(tid - 128) * 2 + 1] = acc2[1];
        }
        __syncthreads();

        float hn[4];
        if (jo < 4) {
            add2(acc2[0], Rs[tid * 2]);
            add2(acc2[1], Rs[tid * 2 + 1]);
            float w[4];
            up2(acc2[0], w[0], w[1]);
            up2(acc2[1], w[2], w[3]);
            #pragma unroll
            for (int j = 0; j < 4; j++) {
                int jl = j2 + j;
                float z  = Zs[jl * 32 + b];
                float ho = HsSv[jl * 32 + b];
                float cand = tanhfast(w[j]);
                float v = z * ho + (1.0f - z) * cand;
                hn[j] = fminf(5.0f, fmaxf(-5.0f, v));
                __stcg(myH + (d0 + jl) * 32 + b, hn[j]);
            }
        }
        __syncthreads();
        if (tid == 0) { __threadfence(); atomicAdd(my_h, 1u); }

        // ci outputs off the fenced path
        if (g >= 2 && s < Tn - 1 && jo < 4) {
            int Bg = pg * 32 + b;
            size_t row = (g == 2)
                ? ((size_t)Bg * Tn + s + 1) * 512 + d0 + j2
                : ((size_t)Bg * Tn + (Tn - 2 - s)) * 512 + 256 + d0 + j2;
            __stcg((float4*)(ci + row), make_float4(hn[0], hn[1], hn[2], hn[3]));
        }
    }

    // ================= fused heads (ic GRUs only, 128 CTAs) =================
    if (g < 2) {
        __syncthreads();
        if (tid == 0) {
            __threadfence();
            atomicAdd(&g_headbar, 1u);
            while (*((volatile unsigned*)&g_headbar) < 128u) { __nanosleep(64); }
            __threadfence();
        }
        __syncthreads();

        int bat = g * 64 + pg * 16 + cs;      // 0..127, one batch per CTA
        int pgr = bat >> 5, b32 = bat & 31;
        float* hn0 = U1s;
        for (int i = tid; i < 512; i += 256)
            hn0[i] = (i < 256) ? g_H[pgr * 8192 + i * 32 + b32]
                               : g_H[(4 + pgr) * 8192 + (i - 256) * 32 + b32];
        __syncthreads();
        if (tid < 128) {
            int m = tid;
            float am = bm[m], alv = blv[m];
            for (int k = 0; k < 512; k++) {
                float h = hn0[k];
                am  += h * Wm [k * 128 + m];
                alv += h * Wlv[k * 128 + m];
            }
            out[bat * 128 + m] = am;
            out[16384 + bat * 128 + m] = sqrtf(expf(alv) + 1e-4f);
        }
    }
}

// ---------------- launch ----------------
extern "C" void kernel_launch(void* const* d_in, const int* in_sizes, int n_in,
                              void* d_out, int out_size) {
    const float* data = (const float*)d_in[0];
    const float* icWf = (const float*)d_in[1];
    const float* icUf = (const float*)d_in[2];
    const float* icbf = (const float*)d_in[3];
    const float* icWb = (const float*)d_in[4];
    const float* icUb = (const float*)d_in[5];
    const float* icbb = (const float*)d_in[6];
    const float* ich0 = (const float*)d_in[7];
    const float* ciWf = (const float*)d_in[8];
    const float* ciUf = (const float*)d_in[9];
    const float* cibf = (const float*)d_in[10];
    const float* ciWb = (const float*)d_in[11];
    const float* ciUb = (const float*)d_in[12];
    const float* cibb = (const float*)d_in[13];
    const float* cih0 = (const float*)d_in[14];
    const float* Wm   = (const float*)d_in[15];
    const float* bm   = (const float*)d_in[16];
    const float* Wlv  = (const float*)d_in[17];
    const float* blv  = (const float*)d_in[18];
    float* out = (float*)d_out;

    cudaFuncSetAttribute(scan_kernel, cudaFuncAttributeMaxDynamicSharedMemorySize,
                         SCAN_SMEM_BYTES);

    dim3 grid(24, Tn);
    xproj_kernel<<<grid, 256>>>(data, icWf, icWb, ciWf, ciWb,
                                icbf, icbb, cibf, cibb,
                                ich0, cih0, out);

    scan_kernel<<<256, 256, SCAN_SMEM_BYTES>>>(icUf, icUb, ciUf, ciUb,
                                               Wm, bm, Wlv, blv, out);
}